// round 15
// baseline (speedup 1.0000x reference)
#include <cuda_runtime.h>
#include <cuda_fp16.h>

#define B_ 16
#define N_ 512
#define H_ 8
#define D_ 64
#define BM 128
#define BN 64
#define NTILES 8
// C2 = 8*log2(e): base-2 logit scale (sqrt(D)=8 folded); C4 = 2*C2 pre-applied to Q
#define C2 11.541560327111707f
#define C4 23.083120654223414f

// per-stage smem byte offsets (stage = K hi/lo + V hi + k2c), plus static ones tile
#define KHI 0
#define KLO 8192
#define VHI 16384
#define K2C 24576
#define STG 24832
#define ONES (2*STG)
#define SMEM_BYTES (ONES + 1024)

typedef unsigned int u32;

__device__ __forceinline__ u32 swz(u32 x){ return x ^ ((x >> 3) & 0x70u); }

__device__ __forceinline__ u32 s2u(const void* p){
  u32 a; asm("{ .reg .u64 t; cvta.to.shared.u64 t, %1; cvt.u32.u64 %0, t; }" : "=r"(a) : "l"(p));
  return a;
}
__device__ __forceinline__ float ex2(float x){
  float r; asm("ex2.approx.f32 %0, %1;" : "=f"(r) : "f"(x)); return r;
}
// pack (lo,hi) fp32 -> fp16x2, then exp2 both halves (result is a ready A-fragment half)
__device__ __forceinline__ u32 ex2pk(float lo, float hi){
  u32 r;
  asm("{\n\t.reg .b32 t;\n\tcvt.rn.f16x2.f32 t, %2, %1;\n\tex2.approx.f16x2 %0, t;\n\t}"
      : "=r"(r) : "f"(lo), "f"(hi));
  return r;
}
__device__ __forceinline__ void pfl1(const void* p){
  asm volatile("prefetch.global.L1 [%0];" :: "l"(p) : "memory");
}
__device__ __forceinline__ u32 packsplit(float a, float b, u32& lo){
  __half ha = __float2half_rn(a), hb = __float2half_rn(b);
  __half la = __float2half_rn(a - __half2float(ha));
  __half lb = __float2half_rn(b - __half2float(hb));
  lo = (u32)__half_as_ushort(la) | ((u32)__half_as_ushort(lb) << 16);
  return (u32)__half_as_ushort(ha) | ((u32)__half_as_ushort(hb) << 16);
}
__device__ __forceinline__ u32 packh(float a, float b){
  __half ha = __float2half_rn(a), hb = __float2half_rn(b);
  return (u32)__half_as_ushort(ha) | ((u32)__half_as_ushort(hb) << 16);
}
__device__ __forceinline__ void mma16816(float* c, u32 a0, u32 a1, u32 a2, u32 a3,
                                         u32 b0, u32 b1){
  asm volatile(
    "mma.sync.aligned.m16n8k16.row.col.f32.f16.f16.f32 "
    "{%0,%1,%2,%3}, {%4,%5,%6,%7}, {%8,%9}, {%0,%1,%2,%3};"
    : "+f"(c[0]), "+f"(c[1]), "+f"(c[2]), "+f"(c[3])
    : "r"(a0), "r"(a1), "r"(a2), "r"(a3), "r"(b0), "r"(b1));
}
__device__ __forceinline__ void ldm4(u32 addr, u32& r0, u32& r1, u32& r2, u32& r3){
  asm volatile("ldmatrix.sync.aligned.m8n8.x4.shared.b16 {%0,%1,%2,%3}, [%4];"
    : "=r"(r0), "=r"(r1), "=r"(r2), "=r"(r3) : "r"(addr));
}
__device__ __forceinline__ void ldm4t(u32 addr, u32& r0, u32& r1, u32& r2, u32& r3){
  asm volatile("ldmatrix.sync.aligned.m8n8.x4.trans.shared.b16 {%0,%1,%2,%3}, [%4];"
    : "=r"(r0), "=r"(r1), "=r"(r2), "=r"(r3) : "r"(addr));
}
__device__ __forceinline__ void ldm2t(u32 addr, u32& r0, u32& r1){
  asm volatile("ldmatrix.sync.aligned.m8n8.x2.trans.shared.b16 {%0,%1}, [%2];"
    : "=r"(r0), "=r"(r1) : "r"(addr));
}

// R12 inline K/V tile load: LDG fp32 -> fp16 hi/lo convert -> swizzled STS
__device__ __forceinline__ void load_tile(char* smc, u32 st,
    const float* __restrict__ ksrc0, const float* __restrict__ vsrc0, int tid){
  const int r = tid >> 2, c4 = tid & 3, d0 = c4 * 16;
  const float* ksrc = ksrc0 + (size_t)r*(H_*D_) + d0;
  const float* vsrc = vsrc0 + (size_t)r*(H_*D_) + d0;
  const u32 o0 = swz((u32)(r*128 + d0*2));
  const u32 o1 = swz((u32)(r*128 + d0*2 + 16));
  float k2p = 0.f;
  {
    u32 hp[8], lp[8];
    #pragma unroll
    for (int c = 0; c < 4; c++){
      float4 x = *(const float4*)(ksrc + c*4);
      k2p += x.x*x.x + x.y*x.y + x.z*x.z + x.w*x.w;
      hp[c*2]   = packsplit(x.x, x.y, lp[c*2]);
      hp[c*2+1] = packsplit(x.z, x.w, lp[c*2+1]);
    }
    *(uint4*)(smc + st + KHI + o0) = make_uint4(hp[0], hp[1], hp[2], hp[3]);
    *(uint4*)(smc + st + KHI + o1) = make_uint4(hp[4], hp[5], hp[6], hp[7]);
    *(uint4*)(smc + st + KLO + o0) = make_uint4(lp[0], lp[1], lp[2], lp[3]);
    *(uint4*)(smc + st + KLO + o1) = make_uint4(lp[4], lp[5], lp[6], lp[7]);
  }
  k2p += __shfl_xor_sync(0xffffffffu, k2p, 1);
  k2p += __shfl_xor_sync(0xffffffffu, k2p, 2);
  if (c4 == 0) ((float*)(smc + st + K2C))[r] = C2 * k2p;
  {
    u32 vp[8];
    #pragma unroll
    for (int c = 0; c < 4; c++){
      float4 x = *(const float4*)(vsrc + c*4);
      vp[c*2]   = packh(x.x, x.y);
      vp[c*2+1] = packh(x.z, x.w);
    }
    *(uint4*)(smc + st + VHI + o0) = make_uint4(vp[0], vp[1], vp[2], vp[3]);
    *(uint4*)(smc + st + VHI + o1) = make_uint4(vp[4], vp[5], vp[6], vp[7]);
  }
}

__global__ void __launch_bounds__(256, 2) geo_attn_mma(
    const float* __restrict__ q, const float* __restrict__ k,
    const float* __restrict__ v, const float* __restrict__ geo,
    float* __restrict__ out)
{
  extern __shared__ __align__(128) char smc[];
  const u32 smb = s2u(smc);
  const int tid = threadIdx.x, w = tid >> 5, l = tid & 31;
  const int qr = l >> 2;
  const int qc = l & 3;
  const int r0 = w * 16 + qr;
  const int qt = blockIdx.x, h = blockIdx.y, b = blockIdx.z;
  const int n0 = qt * BM;
  const int rowstride = H_ * D_;

  const u32 kfrag = (u32)((l & 7) * 128 + (l >> 3) * 16);
  const u32 vfrag = (u32)(((l >> 3) & 1) * 1024 + (l & 7) * 128 + (l >> 4) * 16);
  // ones tile lane address (16B rows, keys as rows, mirrors V orientation)
  const u32 ofrag = (u32)((((l >> 3) & 1) * 8 + (l & 7)) * 16);

  const float* kb = k + ((size_t)b*N_*H_ + h)*D_;
  const float* vb = v + ((size_t)b*N_*H_ + h)*D_;

  // per-lane geo L1-prefetch base: lane covers row w*16+(l&15), 128B line (l>>4)
  const float* gpre = geo + (size_t)b*(N_*N_)
                    + (size_t)(n0 + w*16 + (l & 15))*N_ + (l >> 4)*32;

  // ---- static ones tile: 64 key-rows x 8 cols fp16, col0 = 1.0 ----
  if (tid < 64)
    *(uint4*)(smc + ONES + tid*16) = make_uint4(0x00003C00u, 0u, 0u, 0u);

  // ---- Q A-fragments from global, pre-scaled by 2*C2, fp16 hi/lo split ----
  u32 aqh[4][4], aql[4][4];
  {
    const float* qb = q + ((size_t)(b*N_ + n0 + r0)*H_ + h)*D_;
    #pragma unroll
    for (int ks = 0; ks < 4; ks++){
      const int c0 = ks*16 + qc*2;
      float2 x00 = *(const float2*)(qb + c0);
      float2 x10 = *(const float2*)(qb + 8*rowstride + c0);
      float2 x01 = *(const float2*)(qb + c0 + 8);
      float2 x11 = *(const float2*)(qb + 8*rowstride + c0 + 8);
      aqh[ks][0] = packsplit(C4*x00.x, C4*x00.y, aql[ks][0]);
      aqh[ks][1] = packsplit(C4*x10.x, C4*x10.y, aql[ks][1]);
      aqh[ks][2] = packsplit(C4*x01.x, C4*x01.y, aql[ks][2]);
      aqh[ks][3] = packsplit(C4*x11.x, C4*x11.y, aql[ks][3]);
    }
  }

  float oacc[NTILES][4];
  #pragma unroll
  for (int t = 0; t < NTILES; t++){
    oacc[t][0]=0.f; oacc[t][1]=0.f; oacc[t][2]=0.f; oacc[t][3]=0.f;
  }
  float lsacc[4];
  lsacc[0]=0.f; lsacc[1]=0.f; lsacc[2]=0.f; lsacc[3]=0.f;
  float mold0 = -1e30f, mold1 = -1e30f;

  const float* grow = geo + (size_t)b*(N_*N_) + (size_t)(n0 + r0)*N_ + qc*2;

  // prologue: prefetch geo(0) to L1, then fill stage 0
  pfl1(gpre);
  load_tile(smc, 0, kb, vb, tid);
  __syncthreads();

  for (int mt = 0; mt < NTILES; mt++){
    const int m0 = mt * BN;
    const u32 sto = (u32)(mt & 1) * STG;
    const u32 st  = smb + sto;

    // L1-prefetch geo(t+1) lines this warp's softmax will read next iteration
    if (mt < NTILES-1) pfl1(gpre + m0 + BN);

    // prefetch next tile into the other stage (R12 inline style)
    if (mt < NTILES-1){
      load_tile(smc, (u32)((mt+1) & 1) * STG,
                kb + (size_t)(m0+BN)*rowstride, vb + (size_t)(m0+BN)*rowstride, tid);
    }

    // ---- S = Q @ K^T (3-term fp16 split) ----
    float sacc[NTILES][4];
    #pragma unroll
    for (int t = 0; t < NTILES; t++){
      sacc[t][0]=0.f; sacc[t][1]=0.f; sacc[t][2]=0.f; sacc[t][3]=0.f;
    }
    #pragma unroll
    for (int ks2 = 0; ks2 < 2; ks2++){
      const int ka = 2*ks2, kb2 = 2*ks2 + 1;
      #pragma unroll
      for (int nt = 0; nt < NTILES; nt++){
        const u32 off = swz(kfrag + (u32)(nt*1024 + ks2*64));
        u32 h0,h1,h2,h3, l0,l1,l2,l3;
        ldm4(st + KHI + off, h0, h1, h2, h3);
        ldm4(st + KLO + off, l0, l1, l2, l3);
        mma16816(sacc[nt], aqh[ka][0], aqh[ka][1], aqh[ka][2], aqh[ka][3], h0, h1);
        mma16816(sacc[nt], aqh[ka][0], aqh[ka][1], aqh[ka][2], aqh[ka][3], l0, l1);
        mma16816(sacc[nt], aql[ka][0], aql[ka][1], aql[ka][2], aql[ka][3], h0, h1);
        mma16816(sacc[nt], aqh[kb2][0], aqh[kb2][1], aqh[kb2][2], aqh[kb2][3], h2, h3);
        mma16816(sacc[nt], aqh[kb2][0], aqh[kb2][1], aqh[kb2][2], aqh[kb2][3], l2, l3);
        mma16816(sacc[nt], aql[kb2][0], aql[kb2][1], aql[kb2][2], aql[kb2][3], h2, h3);
      }
    }

    // ---- logits + online softmax ----
    float mx0 = -1e30f, mx1 = -1e30f;
    #pragma unroll
    for (int nt = 0; nt < NTILES; nt++){
      const float2 kk = *(const float2*)((const float*)(smc + sto + K2C) + nt*8 + qc*2);
      const float2 g0 = *(const float2*)(grow + m0 + nt*8);
      const float2 g1 = *(const float2*)(grow + 8*N_ + m0 + nt*8);
      float t00 = fmaf(C2, g0.x, sacc[nt][0] - kk.x);
      float t01 = fmaf(C2, g0.y, sacc[nt][1] - kk.y);
      float t10 = fmaf(C2, g1.x, sacc[nt][2] - kk.x);
      float t11 = fmaf(C2, g1.y, sacc[nt][3] - kk.y);
      sacc[nt][0]=t00; sacc[nt][1]=t01; sacc[nt][2]=t10; sacc[nt][3]=t11;
      mx0 = fmaxf(mx0, fmaxf(t00, t01));
      mx1 = fmaxf(mx1, fmaxf(t10, t11));
    }
    #pragma unroll
    for (int d = 1; d < 4; d <<= 1){
      mx0 = fmaxf(mx0, __shfl_xor_sync(0xffffffffu, mx0, d));
      mx1 = fmaxf(mx1, __shfl_xor_sync(0xffffffffu, mx1, d));
    }
    const float mnew0 = fmaxf(mold0, mx0), mnew1 = fmaxf(mold1, mx1);
    const float al0 = ex2(mold0 - mnew0), al1 = ex2(mold1 - mnew1);
    mold0 = mnew0; mold1 = mnew1;

    // exp in fp16x2 — output doubles as the packed PV A-fragments (no fp32 unpack)
    u32 pfr[16];
    #pragma unroll
    for (int nt = 0; nt < NTILES; nt++){
      pfr[nt*2]   = ex2pk(sacc[nt][0] - mnew0, sacc[nt][1] - mnew0);
      pfr[nt*2+1] = ex2pk(sacc[nt][2] - mnew1, sacc[nt][3] - mnew1);
    }
    #pragma unroll
    for (int t = 0; t < NTILES; t++){
      oacc[t][0]*=al0; oacc[t][1]*=al0; oacc[t][2]*=al1; oacc[t][3]*=al1;
    }
    lsacc[0]*=al0; lsacc[1]*=al0; lsacc[2]*=al1; lsacc[3]*=al1;

    // ---- O += P @ V ; ls += P @ ones (row sums via tensor pipe) ----
    #pragma unroll
    for (int ks = 0; ks < 4; ks++){
      const u32 a0 = pfr[4*ks+0], a1 = pfr[4*ks+1];
      const u32 a2 = pfr[4*ks+2], a3 = pfr[4*ks+3];
      {
        u32 ob0, ob1;
        ldm2t(smb + ONES + (u32)(ks*256) + ofrag, ob0, ob1);
        mma16816(lsacc, a0, a1, a2, a3, ob0, ob1);
      }
      #pragma unroll
      for (int dt2 = 0; dt2 < 4; dt2++){
        const u32 off = swz(vfrag + (u32)(ks*2048 + dt2*32));
        u32 h0,h1,h2,h3;
        ldm4t(st + VHI + off, h0, h1, h2, h3);
        mma16816(oacc[2*dt2],   a0, a1, a2, a3, h0, h1);
        mma16816(oacc[2*dt2+1], a0, a1, a2, a3, h2, h3);
      }
    }

    __syncthreads();   // stage reads done; next iter may overwrite
  }

  // ---- epilogue: ls lives in col0 of the lsacc fragment (qc==0 lanes) ----
  {
    const float ls0 = __shfl_sync(0xffffffffu, lsacc[0], l & 28);
    const float ls1 = __shfl_sync(0xffffffffu, lsacc[2], l & 28);
    const float inv0 = 1.f / ls0, inv1 = 1.f / ls1;
    float* ob = out + ((size_t)(b*N_ + n0 + r0)*H_ + h)*D_ + qc*2;
    #pragma unroll
    for (int dt = 0; dt < NTILES; dt++){
      float2 r4a; r4a.x = oacc[dt][0]*inv0; r4a.y = oacc[dt][1]*inv0;
      float2 r4b; r4b.x = oacc[dt][2]*inv1; r4b.y = oacc[dt][3]*inv1;
      *(float2*)(ob + dt*8) = r4a;
      *(float2*)(ob + 8*rowstride + dt*8) = r4b;
    }
  }
}

extern "C" void kernel_launch(void* const* d_in, const int* in_sizes, int n_in,
                              void* d_out, int out_size) {
  const float* q = (const float*)d_in[0];
  const float* k = (const float*)d_in[1];
  const float* v = (const float*)d_in[2];
  const float* g = (const float*)d_in[3];
  float* out = (float*)d_out;

  cudaFuncSetAttribute(geo_attn_mma, cudaFuncAttributeMaxDynamicSharedMemorySize, SMEM_BYTES);
  dim3 grid(N_/BM, H_, B_);
  geo_attn_mma<<<grid, 256, SMEM_BYTES>>>(q, k, v, g, out);
}

// round 16
// speedup vs baseline: 1.5240x; 1.5240x over previous
#include <cuda_runtime.h>
#include <cuda_fp16.h>

#define B_ 16
#define N_ 512
#define H_ 8
#define D_ 64
#define BM 128
#define BN 64
#define NTILES 8
// C2 = 8*log2(e): base-2 logit scale (sqrt(D)=8 folded); C4 = 2*C2 pre-applied to Q
#define C2 11.541560327111707f
#define C4 23.083120654223414f

// per-stage smem byte offsets (stage = K hi/lo + V hi + k2c)
#define KHI 0
#define KLO 8192
#define VHI 16384
#define K2C 24576
#define STG 24832
#define SMEM_BYTES (2*STG)

typedef unsigned int u32;

__device__ __forceinline__ u32 swz(u32 x){ return x ^ ((x >> 3) & 0x70u); }

__device__ __forceinline__ u32 s2u(const void* p){
  u32 a; asm("{ .reg .u64 t; cvta.to.shared.u64 t, %1; cvt.u32.u64 %0, t; }" : "=r"(a) : "l"(p));
  return a;
}
__device__ __forceinline__ float ex2(float x){
  float r; asm("ex2.approx.f32 %0, %1;" : "=f"(r) : "f"(x)); return r;
}
// pack (lo,hi) fp32 -> fp16x2, then exp2 both halves (result is a ready A-fragment half)
__device__ __forceinline__ u32 ex2pk(float lo, float hi){
  u32 r;
  asm("{\n\t.reg .b32 t;\n\tcvt.rn.f16x2.f32 t, %2, %1;\n\tex2.approx.f16x2 %0, t;\n\t}"
      : "=r"(r) : "f"(lo), "f"(hi));
  return r;
}
__device__ __forceinline__ void pfl1(const void* p){
  asm volatile("prefetch.global.L1 [%0];" :: "l"(p) : "memory");
}
__device__ __forceinline__ u32 packsplit(float a, float b, u32& lo){
  __half ha = __float2half_rn(a), hb = __float2half_rn(b);
  __half la = __float2half_rn(a - __half2float(ha));
  __half lb = __float2half_rn(b - __half2float(hb));
  lo = (u32)__half_as_ushort(la) | ((u32)__half_as_ushort(lb) << 16);
  return (u32)__half_as_ushort(ha) | ((u32)__half_as_ushort(hb) << 16);
}
__device__ __forceinline__ u32 packh(float a, float b){
  __half ha = __float2half_rn(a), hb = __float2half_rn(b);
  return (u32)__half_as_ushort(ha) | ((u32)__half_as_ushort(hb) << 16);
}
__device__ __forceinline__ void mma16816(float* c, u32 a0, u32 a1, u32 a2, u32 a3,
                                         u32 b0, u32 b1){
  asm volatile(
    "mma.sync.aligned.m16n8k16.row.col.f32.f16.f16.f32 "
    "{%0,%1,%2,%3}, {%4,%5,%6,%7}, {%8,%9}, {%0,%1,%2,%3};"
    : "+f"(c[0]), "+f"(c[1]), "+f"(c[2]), "+f"(c[3])
    : "r"(a0), "r"(a1), "r"(a2), "r"(a3), "r"(b0), "r"(b1));
}
__device__ __forceinline__ void ldm4(u32 addr, u32& r0, u32& r1, u32& r2, u32& r3){
  asm volatile("ldmatrix.sync.aligned.m8n8.x4.shared.b16 {%0,%1,%2,%3}, [%4];"
    : "=r"(r0), "=r"(r1), "=r"(r2), "=r"(r3) : "r"(addr));
}
__device__ __forceinline__ void ldm4t(u32 addr, u32& r0, u32& r1, u32& r2, u32& r3){
  asm volatile("ldmatrix.sync.aligned.m8n8.x4.trans.shared.b16 {%0,%1,%2,%3}, [%4];"
    : "=r"(r0), "=r"(r1), "=r"(r2), "=r"(r3) : "r"(addr));
}

// R5 inline K/V tile load: LDG fp32 -> fp16 hi/lo convert -> swizzled STS
__device__ __forceinline__ void load_tile(char* smc, u32 st,
    const float* __restrict__ ksrc0, const float* __restrict__ vsrc0, int tid){
  const int r = tid >> 2, c4 = tid & 3, d0 = c4 * 16;
  const float* ksrc = ksrc0 + (size_t)r*(H_*D_) + d0;
  const float* vsrc = vsrc0 + (size_t)r*(H_*D_) + d0;
  const u32 o0 = swz((u32)(r*128 + d0*2));
  const u32 o1 = swz((u32)(r*128 + d0*2 + 16));
  float k2p = 0.f;
  {
    u32 hp[8], lp[8];
    #pragma unroll
    for (int c = 0; c < 4; c++){
      float4 x = *(const float4*)(ksrc + c*4);
      k2p += x.x*x.x + x.y*x.y + x.z*x.z + x.w*x.w;
      hp[c*2]   = packsplit(x.x, x.y, lp[c*2]);
      hp[c*2+1] = packsplit(x.z, x.w, lp[c*2+1]);
    }
    *(uint4*)(smc + st + KHI + o0) = make_uint4(hp[0], hp[1], hp[2], hp[3]);
    *(uint4*)(smc + st + KHI + o1) = make_uint4(hp[4], hp[5], hp[6], hp[7]);
    *(uint4*)(smc + st + KLO + o0) = make_uint4(lp[0], lp[1], lp[2], lp[3]);
    *(uint4*)(smc + st + KLO + o1) = make_uint4(lp[4], lp[5], lp[6], lp[7]);
  }
  k2p += __shfl_xor_sync(0xffffffffu, k2p, 1);
  k2p += __shfl_xor_sync(0xffffffffu, k2p, 2);
  if (c4 == 0) ((float*)(smc + st + K2C))[r] = C2 * k2p;
  {
    u32 vp[8];
    #pragma unroll
    for (int c = 0; c < 4; c++){
      float4 x = *(const float4*)(vsrc + c*4);
      vp[c*2]   = packh(x.x, x.y);
      vp[c*2+1] = packh(x.z, x.w);
    }
    *(uint4*)(smc + st + VHI + o0) = make_uint4(vp[0], vp[1], vp[2], vp[3]);
    *(uint4*)(smc + st + VHI + o1) = make_uint4(vp[4], vp[5], vp[6], vp[7]);
  }
}

__global__ void __launch_bounds__(256, 2) geo_attn_mma(
    const float* __restrict__ q, const float* __restrict__ k,
    const float* __restrict__ v, const float* __restrict__ geo,
    float* __restrict__ out)
{
  extern __shared__ __align__(128) char smc[];
  const u32 smb = s2u(smc);
  const int tid = threadIdx.x, w = tid >> 5, l = tid & 31;
  const int qr = l >> 2;
  const int qc = l & 3;
  const int r0 = w * 16 + qr;
  const int qt = blockIdx.x, h = blockIdx.y, b = blockIdx.z;
  const int n0 = qt * BM;
  const int rowstride = H_ * D_;

  const u32 kfrag = (u32)((l & 7) * 128 + (l >> 3) * 16);
  const u32 vfrag = (u32)(((l >> 3) & 1) * 1024 + (l & 7) * 128 + (l >> 4) * 16);

  const float* kb = k + ((size_t)b*N_*H_ + h)*D_;
  const float* vb = v + ((size_t)b*N_*H_ + h)*D_;

  // per-lane geo L1-prefetch base: lane covers row w*16+(l&15), 128B line (l>>4)
  const float* gpre = geo + (size_t)b*(N_*N_)
                    + (size_t)(n0 + w*16 + (l & 15))*N_ + (l >> 4)*32;

  // ---- Q A-fragments from global, pre-scaled by 2*C2, fp16 hi/lo split ----
  u32 aqh[4][4], aql[4][4];
  {
    const float* qb = q + ((size_t)(b*N_ + n0 + r0)*H_ + h)*D_;
    #pragma unroll
    for (int ks = 0; ks < 4; ks++){
      const int c0 = ks*16 + qc*2;
      float2 x00 = *(const float2*)(qb + c0);
      float2 x10 = *(const float2*)(qb + 8*rowstride + c0);
      float2 x01 = *(const float2*)(qb + c0 + 8);
      float2 x11 = *(const float2*)(qb + 8*rowstride + c0 + 8);
      aqh[ks][0] = packsplit(C4*x00.x, C4*x00.y, aql[ks][0]);
      aqh[ks][1] = packsplit(C4*x10.x, C4*x10.y, aql[ks][1]);
      aqh[ks][2] = packsplit(C4*x01.x, C4*x01.y, aql[ks][2]);
      aqh[ks][3] = packsplit(C4*x11.x, C4*x11.y, aql[ks][3]);
    }
  }

  float oacc[NTILES][4];
  #pragma unroll
  for (int t = 0; t < NTILES; t++){
    oacc[t][0]=0.f; oacc[t][1]=0.f; oacc[t][2]=0.f; oacc[t][3]=0.f;
  }
  float mold0 = -1e30f, mold1 = -1e30f, ls0 = 0.f, ls1 = 0.f;

  const float* grow = geo + (size_t)b*(N_*N_) + (size_t)(n0 + r0)*N_ + qc*2;

  // prologue: prefetch geo(0) to L1, then fill stage 0
  pfl1(gpre);
  load_tile(smc, 0, kb, vb, tid);
  __syncthreads();

  for (int mt = 0; mt < NTILES; mt++){
    const int m0 = mt * BN;
    const u32 sto = (u32)(mt & 1) * STG;
    const u32 st  = smb + sto;

    // L1-prefetch geo(t+1) lines this warp's softmax will read next iteration
    if (mt < NTILES-1) pfl1(gpre + m0 + BN);

    // prefetch next tile into the other stage (R5 inline style)
    if (mt < NTILES-1){
      load_tile(smc, (u32)((mt+1) & 1) * STG,
                kb + (size_t)(m0+BN)*rowstride, vb + (size_t)(m0+BN)*rowstride, tid);
    }

    // ---- S = Q @ K^T (3-term fp16 split) ----
    float sacc[NTILES][4];
    #pragma unroll
    for (int t = 0; t < NTILES; t++){
      sacc[t][0]=0.f; sacc[t][1]=0.f; sacc[t][2]=0.f; sacc[t][3]=0.f;
    }
    #pragma unroll
    for (int ks2 = 0; ks2 < 2; ks2++){
      const int ka = 2*ks2, kb2 = 2*ks2 + 1;
      #pragma unroll
      for (int nt = 0; nt < NTILES; nt++){
        const u32 off = swz(kfrag + (u32)(nt*1024 + ks2*64));
        u32 h0,h1,h2,h3, l0,l1,l2,l3;
        ldm4(st + KHI + off, h0, h1, h2, h3);
        ldm4(st + KLO + off, l0, l1, l2, l3);
        mma16816(sacc[nt], aqh[ka][0], aqh[ka][1], aqh[ka][2], aqh[ka][3], h0, h1);
        mma16816(sacc[nt], aqh[ka][0], aqh[ka][1], aqh[ka][2], aqh[ka][3], l0, l1);
        mma16816(sacc[nt], aql[ka][0], aql[ka][1], aql[ka][2], aql[ka][3], h0, h1);
        mma16816(sacc[nt], aqh[kb2][0], aqh[kb2][1], aqh[kb2][2], aqh[kb2][3], h2, h3);
        mma16816(sacc[nt], aqh[kb2][0], aqh[kb2][1], aqh[kb2][2], aqh[kb2][3], l2, l3);
        mma16816(sacc[nt], aql[kb2][0], aql[kb2][1], aql[kb2][2], aql[kb2][3], h2, h3);
      }
    }

    // ---- logits + online softmax ----
    float mx0 = -1e30f, mx1 = -1e30f;
    #pragma unroll
    for (int nt = 0; nt < NTILES; nt++){
      const float2 kk = *(const float2*)((const float*)(smc + sto + K2C) + nt*8 + qc*2);
      const float2 g0 = *(const float2*)(grow + m0 + nt*8);
      const float2 g1 = *(const float2*)(grow + 8*N_ + m0 + nt*8);
      float t00 = fmaf(C2, g0.x, sacc[nt][0] - kk.x);
      float t01 = fmaf(C2, g0.y, sacc[nt][1] - kk.y);
      float t10 = fmaf(C2, g1.x, sacc[nt][2] - kk.x);
      float t11 = fmaf(C2, g1.y, sacc[nt][3] - kk.y);
      sacc[nt][0]=t00; sacc[nt][1]=t01; sacc[nt][2]=t10; sacc[nt][3]=t11;
      mx0 = fmaxf(mx0, fmaxf(t00, t01));
      mx1 = fmaxf(mx1, fmaxf(t10, t11));
    }
    #pragma unroll
    for (int d = 1; d < 4; d <<= 1){
      mx0 = fmaxf(mx0, __shfl_xor_sync(0xffffffffu, mx0, d));
      mx1 = fmaxf(mx1, __shfl_xor_sync(0xffffffffu, mx1, d));
    }
    const float mnew0 = fmaxf(mold0, mx0), mnew1 = fmaxf(mold1, mx1);
    const float al0 = ex2(mold0 - mnew0), al1 = ex2(mold1 - mnew1);
    mold0 = mnew0; mold1 = mnew1;

    // exp in fp16x2 — output doubles as the packed PV A-fragments
    u32 pfr[16];
    float ps0 = 0.f, ps1 = 0.f;
    #pragma unroll
    for (int nt = 0; nt < NTILES; nt++){
      const u32 pa = ex2pk(sacc[nt][0] - mnew0, sacc[nt][1] - mnew0);
      const u32 pb = ex2pk(sacc[nt][2] - mnew1, sacc[nt][3] - mnew1);
      pfr[nt*2]   = pa;
      pfr[nt*2+1] = pb;
      const float2 fa = __half22float2(*reinterpret_cast<const __half2*>(&pa));
      const float2 fb = __half22float2(*reinterpret_cast<const __half2*>(&pb));
      ps0 += fa.x + fa.y;
      ps1 += fb.x + fb.y;
    }
    ls0 = ls0*al0 + ps0;     // lane-partial; reduced once in epilogue
    ls1 = ls1*al1 + ps1;
    #pragma unroll
    for (int t = 0; t < NTILES; t++){
      oacc[t][0]*=al0; oacc[t][1]*=al0; oacc[t][2]*=al1; oacc[t][3]*=al1;
    }

    // ---- O += P @ V ----
    #pragma unroll
    for (int ks = 0; ks < 4; ks++){
      const u32 a0 = pfr[4*ks+0], a1 = pfr[4*ks+1];
      const u32 a2 = pfr[4*ks+2], a3 = pfr[4*ks+3];
      #pragma unroll
      for (int dt2 = 0; dt2 < 4; dt2++){
        const u32 off = swz(vfrag + (u32)(ks*2048 + dt2*32));
        u32 h0,h1,h2,h3;
        ldm4t(st + VHI + off, h0, h1, h2, h3);
        mma16816(oacc[2*dt2],   a0, a1, a2, a3, h0, h1);
        mma16816(oacc[2*dt2+1], a0, a1, a2, a3, h2, h3);
      }
    }

    __syncthreads();   // stage reads done; next iter may overwrite
  }

  // ---- epilogue (deferred lane reduction of l) ----
  {
    #pragma unroll
    for (int d = 1; d < 4; d <<= 1){
      ls0 += __shfl_xor_sync(0xffffffffu, ls0, d);
      ls1 += __shfl_xor_sync(0xffffffffu, ls1, d);
    }
    const float inv0 = 1.f / ls0, inv1 = 1.f / ls1;
    float* ob = out + ((size_t)(b*N_ + n0 + r0)*H_ + h)*D_ + qc*2;
    #pragma unroll
    for (int dt = 0; dt < NTILES; dt++){
      float2 r4a; r4a.x = oacc[dt][0]*inv0; r4a.y = oacc[dt][1]*inv0;
      float2 r4b; r4b.x = oacc[dt][2]*inv1; r4b.y = oacc[dt][3]*inv1;
      *(float2*)(ob + dt*8) = r4a;
      *(float2*)(ob + 8*rowstride + dt*8) = r4b;
    }
  }
}

extern "C" void kernel_launch(void* const* d_in, const int* in_sizes, int n_in,
                              void* d_out, int out_size) {
  const float* q = (const float*)d_in[0];
  const float* k = (const float*)d_in[1];
  const float* v = (const float*)d_in[2];
  const float* g = (const float*)d_in[3];
  float* out = (float*)d_out;

  cudaFuncSetAttribute(geo_attn_mma, cudaFuncAttributeMaxDynamicSharedMemorySize, SMEM_BYTES);
  dim3 grid(N_/BM, H_, B_);
  geo_attn_mma<<<grid, 256, SMEM_BYTES>>>(q, k, v, g, out);
}

// round 17
// speedup vs baseline: 1.5621x; 1.0250x over previous
#include <cuda_runtime.h>
#include <cuda_fp16.h>

#define B_ 16
#define N_ 512
#define H_ 8
#define D_ 64
#define BM 128
#define BN 64
#define NTILES 8
// C2 = 8*log2(e): base-2 logit scale (sqrt(D)=8 folded); C4 = 2*C2 pre-applied to Q
#define C2 11.541560327111707f
#define C4 23.083120654223414f

// per-stage smem byte offsets (stage = K hi/lo + V hi + k2c[negated])
#define KHI 0
#define KLO 8192
#define VHI 16384
#define K2C 24576
#define STG 24832
#define SMEM_BYTES (2*STG)

typedef unsigned int u32;
typedef unsigned long long u64;

__device__ __forceinline__ u32 swz(u32 x){ return x ^ ((x >> 3) & 0x70u); }

__device__ __forceinline__ u32 s2u(const void* p){
  u32 a; asm("{ .reg .u64 t; cvta.to.shared.u64 t, %1; cvt.u32.u64 %0, t; }" : "=r"(a) : "l"(p));
  return a;
}
__device__ __forceinline__ float ex2(float x){
  float r; asm("ex2.approx.f32 %0, %1;" : "=f"(r) : "f"(x)); return r;
}
// pack (lo,hi) fp32 -> fp16x2, then exp2 both halves (result is a ready A-fragment half)
__device__ __forceinline__ u32 ex2pk(float lo, float hi){
  u32 r;
  asm("{\n\t.reg .b32 t;\n\tcvt.rn.f16x2.f32 t, %2, %1;\n\tex2.approx.f16x2 %0, t;\n\t}"
      : "=r"(r) : "f"(lo), "f"(hi));
  return r;
}
__device__ __forceinline__ void pfl1(const void* p){
  asm volatile("prefetch.global.L1 [%0];" :: "l"(p) : "memory");
}
// ---- packed f32x2 helpers (PTX-only; ptxas never auto-fuses these) ----
__device__ __forceinline__ u64 pack2(float lo, float hi){
  u64 r; asm("mov.b64 %0, {%1, %2};" : "=l"(r) : "f"(lo), "f"(hi)); return r;
}
__device__ __forceinline__ void unpack2(u64 v, float& lo, float& hi){
  asm("mov.b64 {%0, %1}, %2;" : "=f"(lo), "=f"(hi) : "l"(v));
}
__device__ __forceinline__ u64 fadd2(u64 a, u64 b){
  u64 d; asm("add.rn.f32x2 %0, %1, %2;" : "=l"(d) : "l"(a), "l"(b)); return d;
}
__device__ __forceinline__ u64 fmul2(u64 a, u64 b){
  u64 d; asm("mul.rn.f32x2 %0, %1, %2;" : "=l"(d) : "l"(a), "l"(b)); return d;
}
__device__ __forceinline__ u64 ffma2(u64 a, u64 b, u64 c){
  u64 d; asm("fma.rn.f32x2 %0, %1, %2, %3;" : "=l"(d) : "l"(a), "l"(b), "l"(c)); return d;
}
__device__ __forceinline__ u32 packsplit(float a, float b, u32& lo){
  __half ha = __float2half_rn(a), hb = __float2half_rn(b);
  __half la = __float2half_rn(a - __half2float(ha));
  __half lb = __float2half_rn(b - __half2float(hb));
  lo = (u32)__half_as_ushort(la) | ((u32)__half_as_ushort(lb) << 16);
  return (u32)__half_as_ushort(ha) | ((u32)__half_as_ushort(hb) << 16);
}
__device__ __forceinline__ u32 packh(float a, float b){
  __half ha = __float2half_rn(a), hb = __float2half_rn(b);
  return (u32)__half_as_ushort(ha) | ((u32)__half_as_ushort(hb) << 16);
}
__device__ __forceinline__ void mma16816(float* c, u32 a0, u32 a1, u32 a2, u32 a3,
                                         u32 b0, u32 b1){
  asm volatile(
    "mma.sync.aligned.m16n8k16.row.col.f32.f16.f16.f32 "
    "{%0,%1,%2,%3}, {%4,%5,%6,%7}, {%8,%9}, {%0,%1,%2,%3};"
    : "+f"(c[0]), "+f"(c[1]), "+f"(c[2]), "+f"(c[3])
    : "r"(a0), "r"(a1), "r"(a2), "r"(a3), "r"(b0), "r"(b1));
}
__device__ __forceinline__ void ldm4(u32 addr, u32& r0, u32& r1, u32& r2, u32& r3){
  asm volatile("ldmatrix.sync.aligned.m8n8.x4.shared.b16 {%0,%1,%2,%3}, [%4];"
    : "=r"(r0), "=r"(r1), "=r"(r2), "=r"(r3) : "r"(addr));
}
__device__ __forceinline__ void ldm4t(u32 addr, u32& r0, u32& r1, u32& r2, u32& r3){
  asm volatile("ldmatrix.sync.aligned.m8n8.x4.trans.shared.b16 {%0,%1,%2,%3}, [%4];"
    : "=r"(r0), "=r"(r1), "=r"(r2), "=r"(r3) : "r"(addr));
}

// R12 inline K/V tile load; K2C now stores NEGATED C2*||k||^2
__device__ __forceinline__ void load_tile(char* smc, u32 st,
    const float* __restrict__ ksrc0, const float* __restrict__ vsrc0, int tid){
  const int r = tid >> 2, c4 = tid & 3, d0 = c4 * 16;
  const float* ksrc = ksrc0 + (size_t)r*(H_*D_) + d0;
  const float* vsrc = vsrc0 + (size_t)r*(H_*D_) + d0;
  const u32 o0 = swz((u32)(r*128 + d0*2));
  const u32 o1 = swz((u32)(r*128 + d0*2 + 16));
  float k2p = 0.f;
  {
    u32 hp[8], lp[8];
    #pragma unroll
    for (int c = 0; c < 4; c++){
      float4 x = *(const float4*)(ksrc + c*4);
      k2p += x.x*x.x + x.y*x.y + x.z*x.z + x.w*x.w;
      hp[c*2]   = packsplit(x.x, x.y, lp[c*2]);
      hp[c*2+1] = packsplit(x.z, x.w, lp[c*2+1]);
    }
    *(uint4*)(smc + st + KHI + o0) = make_uint4(hp[0], hp[1], hp[2], hp[3]);
    *(uint4*)(smc + st + KHI + o1) = make_uint4(hp[4], hp[5], hp[6], hp[7]);
    *(uint4*)(smc + st + KLO + o0) = make_uint4(lp[0], lp[1], lp[2], lp[3]);
    *(uint4*)(smc + st + KLO + o1) = make_uint4(lp[4], lp[5], lp[6], lp[7]);
  }
  k2p += __shfl_xor_sync(0xffffffffu, k2p, 1);
  k2p += __shfl_xor_sync(0xffffffffu, k2p, 2);
  if (c4 == 0) ((float*)(smc + st + K2C))[r] = -(C2 * k2p);
  {
    u32 vp[8];
    #pragma unroll
    for (int c = 0; c < 4; c++){
      float4 x = *(const float4*)(vsrc + c*4);
      vp[c*2]   = packh(x.x, x.y);
      vp[c*2+1] = packh(x.z, x.w);
    }
    *(uint4*)(smc + st + VHI + o0) = make_uint4(vp[0], vp[1], vp[2], vp[3]);
    *(uint4*)(smc + st + VHI + o1) = make_uint4(vp[4], vp[5], vp[6], vp[7]);
  }
}

__global__ void __launch_bounds__(256, 2) geo_attn_mma(
    const float* __restrict__ q, const float* __restrict__ k,
    const float* __restrict__ v, const float* __restrict__ geo,
    float* __restrict__ out)
{
  extern __shared__ __align__(128) char smc[];
  const u32 smb = s2u(smc);
  const int tid = threadIdx.x, w = tid >> 5, l = tid & 31;
  const int qr = l >> 2;
  const int qc = l & 3;
  const int r0 = w * 16 + qr;
  const int qt = blockIdx.x, h = blockIdx.y, b = blockIdx.z;
  const int n0 = qt * BM;
  const int rowstride = H_ * D_;

  const u32 kfrag = (u32)((l & 7) * 128 + (l >> 3) * 16);
  const u32 vfrag = (u32)(((l >> 3) & 1) * 1024 + (l & 7) * 128 + (l >> 4) * 16);

  const float* kb = k + ((size_t)b*N_*H_ + h)*D_;
  const float* vb = v + ((size_t)b*N_*H_ + h)*D_;

  // per-lane geo L1-prefetch base: lane covers row w*16+(l&15), 128B line (l>>4)
  const float* gpre = geo + (size_t)b*(N_*N_)
                    + (size_t)(n0 + w*16 + (l & 15))*N_ + (l >> 4)*32;

  // ---- Q A-fragments from global, pre-scaled by 2*C2, fp16 hi/lo split ----
  u32 aqh[4][4], aql[4][4];
  {
    const float* qb = q + ((size_t)(b*N_ + n0 + r0)*H_ + h)*D_;
    #pragma unroll
    for (int ks = 0; ks < 4; ks++){
      const int c0 = ks*16 + qc*2;
      float2 x00 = *(const float2*)(qb + c0);
      float2 x10 = *(const float2*)(qb + 8*rowstride + c0);
      float2 x01 = *(const float2*)(qb + c0 + 8);
      float2 x11 = *(const float2*)(qb + 8*rowstride + c0 + 8);
      aqh[ks][0] = packsplit(C4*x00.x, C4*x00.y, aql[ks][0]);
      aqh[ks][1] = packsplit(C4*x10.x, C4*x10.y, aql[ks][1]);
      aqh[ks][2] = packsplit(C4*x01.x, C4*x01.y, aql[ks][2]);
      aqh[ks][3] = packsplit(C4*x11.x, C4*x11.y, aql[ks][3]);
    }
  }

  float oacc[NTILES][4];
  #pragma unroll
  for (int t = 0; t < NTILES; t++){
    oacc[t][0]=0.f; oacc[t][1]=0.f; oacc[t][2]=0.f; oacc[t][3]=0.f;
  }
  float mold0 = -1e30f, mold1 = -1e30f, ls0 = 0.f, ls1 = 0.f;

  const float* grow = geo + (size_t)b*(N_*N_) + (size_t)(n0 + r0)*N_ + qc*2;
  const u64 c2p = pack2(C2, C2);

  // prologue: prefetch geo(0) to L1, then fill stage 0
  pfl1(gpre);
  load_tile(smc, 0, kb, vb, tid);
  __syncthreads();

  for (int mt = 0; mt < NTILES; mt++){
    const int m0 = mt * BN;
    const u32 sto = (u32)(mt & 1) * STG;
    const u32 st  = smb + sto;

    // L1-prefetch geo(t+1) lines this warp's softmax will read next iteration
    if (mt < NTILES-1) pfl1(gpre + m0 + BN);

    // prefetch next tile into the other stage (R12 inline style)
    if (mt < NTILES-1){
      load_tile(smc, (u32)((mt+1) & 1) * STG,
                kb + (size_t)(m0+BN)*rowstride, vb + (size_t)(m0+BN)*rowstride, tid);
    }

    // ---- S = Q @ K^T (3-term fp16 split) ----
    float sacc[NTILES][4];
    #pragma unroll
    for (int t = 0; t < NTILES; t++){
      sacc[t][0]=0.f; sacc[t][1]=0.f; sacc[t][2]=0.f; sacc[t][3]=0.f;
    }
    #pragma unroll
    for (int ks2 = 0; ks2 < 2; ks2++){
      const int ka = 2*ks2, kb2 = 2*ks2 + 1;
      #pragma unroll
      for (int nt = 0; nt < NTILES; nt++){
        const u32 off = swz(kfrag + (u32)(nt*1024 + ks2*64));
        u32 h0,h1,h2,h3, l0,l1,l2,l3;
        ldm4(st + KHI + off, h0, h1, h2, h3);
        ldm4(st + KLO + off, l0, l1, l2, l3);
        mma16816(sacc[nt], aqh[ka][0], aqh[ka][1], aqh[ka][2], aqh[ka][3], h0, h1);
        mma16816(sacc[nt], aqh[ka][0], aqh[ka][1], aqh[ka][2], aqh[ka][3], l0, l1);
        mma16816(sacc[nt], aql[ka][0], aql[ka][1], aql[ka][2], aql[ka][3], h0, h1);
        mma16816(sacc[nt], aqh[kb2][0], aqh[kb2][1], aqh[kb2][2], aqh[kb2][3], h2, h3);
        mma16816(sacc[nt], aqh[kb2][0], aqh[kb2][1], aqh[kb2][2], aqh[kb2][3], l2, l3);
        mma16816(sacc[nt], aql[kb2][0], aql[kb2][1], aql[kb2][2], aql[kb2][3], h2, h3);
      }
    }

    // ---- logits + online softmax (packed f32x2 scalar path) ----
    u64 sp[16];
    float mx0 = -1e30f, mx1 = -1e30f;
    #pragma unroll
    for (int nt = 0; nt < NTILES; nt++){
      const u64 nkk = *(const u64*)((const float*)(smc + sto + K2C) + nt*8 + qc*2);
      const u64 g0p = *(const u64*)(grow + m0 + nt*8);
      const u64 g1p = *(const u64*)(grow + 8*N_ + m0 + nt*8);
      const u64 t01 = ffma2(c2p, g0p, fadd2(pack2(sacc[nt][0], sacc[nt][1]), nkk));
      const u64 t23 = ffma2(c2p, g1p, fadd2(pack2(sacc[nt][2], sacc[nt][3]), nkk));
      sp[nt*2]   = t01;
      sp[nt*2+1] = t23;
      float t00, t01f, t10, t11;
      unpack2(t01, t00, t01f);
      unpack2(t23, t10, t11);
      mx0 = fmaxf(mx0, fmaxf(t00, t01f));
      mx1 = fmaxf(mx1, fmaxf(t10, t11));
    }
    #pragma unroll
    for (int d = 1; d < 4; d <<= 1){
      mx0 = fmaxf(mx0, __shfl_xor_sync(0xffffffffu, mx0, d));
      mx1 = fmaxf(mx1, __shfl_xor_sync(0xffffffffu, mx1, d));
    }
    const float mnew0 = fmaxf(mold0, mx0), mnew1 = fmaxf(mold1, mx1);
    const float al0 = ex2(mold0 - mnew0), al1 = ex2(mold1 - mnew1);
    mold0 = mnew0; mold1 = mnew1;
    const u64 nm0 = pack2(-mnew0, -mnew0), nm1 = pack2(-mnew1, -mnew1);

    // exp in fp16x2 — output doubles as the packed PV A-fragments
    u32 pfr[16];
    u64 psv0 = 0ull, psv1 = 0ull;
    #pragma unroll
    for (int nt = 0; nt < NTILES; nt++){
      float d00, d01, d10, d11;
      unpack2(fadd2(sp[nt*2],   nm0), d00, d01);
      unpack2(fadd2(sp[nt*2+1], nm1), d10, d11);
      const u32 pa = ex2pk(d00, d01);
      const u32 pb = ex2pk(d10, d11);
      pfr[nt*2]   = pa;
      pfr[nt*2+1] = pb;
      const float2 fa = __half22float2(*reinterpret_cast<const __half2*>(&pa));
      const float2 fb = __half22float2(*reinterpret_cast<const __half2*>(&pb));
      psv0 = fadd2(psv0, pack2(fa.x, fa.y));
      psv1 = fadd2(psv1, pack2(fb.x, fb.y));
    }
    {
      float pa, pbf, pc, pd;
      unpack2(psv0, pa, pbf);
      unpack2(psv1, pc, pd);
      ls0 = ls0*al0 + (pa + pbf);   // lane-partial; reduced once in epilogue
      ls1 = ls1*al1 + (pc + pd);
    }
    const u64 a0p = pack2(al0, al0), a1p = pack2(al1, al1);
    #pragma unroll
    for (int t = 0; t < NTILES; t++){
      u64 p01 = fmul2(pack2(oacc[t][0], oacc[t][1]), a0p);
      u64 p23 = fmul2(pack2(oacc[t][2], oacc[t][3]), a1p);
      unpack2(p01, oacc[t][0], oacc[t][1]);
      unpack2(p23, oacc[t][2], oacc[t][3]);
    }

    // ---- O += P @ V ----
    #pragma unroll
    for (int ks = 0; ks < 4; ks++){
      const u32 a0 = pfr[4*ks+0], a1 = pfr[4*ks+1];
      const u32 a2 = pfr[4*ks+2], a3 = pfr[4*ks+3];
      #pragma unroll
      for (int dt2 = 0; dt2 < 4; dt2++){
        const u32 off = swz(vfrag + (u32)(ks*2048 + dt2*32));
        u32 h0,h1,h2,h3;
        ldm4t(st + VHI + off, h0, h1, h2, h3);
        mma16816(oacc[2*dt2],   a0, a1, a2, a3, h0, h1);
        mma16816(oacc[2*dt2+1], a0, a1, a2, a3, h2, h3);
      }
    }

    __syncthreads();   // stage reads done; next iter may overwrite
  }

  // ---- epilogue (deferred lane reduction of l) ----
  {
    #pragma unroll
    for (int d = 1; d < 4; d <<= 1){
      ls0 += __shfl_xor_sync(0xffffffffu, ls0, d);
      ls1 += __shfl_xor_sync(0xffffffffu, ls1, d);
    }
    const float inv0 = 1.f / ls0, inv1 = 1.f / ls1;
    float* ob = out + ((size_t)(b*N_ + n0 + r0)*H_ + h)*D_ + qc*2;
    #pragma unroll
    for (int dt = 0; dt < NTILES; dt++){
      float2 r4a; r4a.x = oacc[dt][0]*inv0; r4a.y = oacc[dt][1]*inv0;
      float2 r4b; r4b.x = oacc[dt][2]*inv1; r4b.y = oacc[dt][3]*inv1;
      *(float2*)(ob + dt*8) = r4a;
      *(float2*)(ob + 8*rowstride + dt*8) = r4b;
    }
  }
}

extern "C" void kernel_launch(void* const* d_in, const int* in_sizes, int n_in,
                              void* d_out, int out_size) {
  const float* q = (const float*)d_in[0];
  const float* k = (const float*)d_in[1];
  const float* v = (const float*)d_in[2];
  const float* g = (const float*)d_in[3];
  float* out = (float*)d_out;

  cudaFuncSetAttribute(geo_attn_mma, cudaFuncAttributeMaxDynamicSharedMemorySize, SMEM_BYTES);
  dim3 grid(N_/BM, H_, B_);
  geo_attn_mma<<<grid, 256, SMEM_BYTES>>>(q, k, v, g, out);
}